// round 6
// baseline (speedup 1.0000x reference)
#include <cuda_runtime.h>

// Shapes (fixed by the problem)
#define Bb 256
#define Cc 256
#define CH 128
#define NN 196               // H*W = 14*14
#define N4 49                // float4s per channel row
#define EPS 1e-5f

#define TPB 256
#define BPG 8                        // blocks per batch
#define GRID (Bb * BPG)              // 2048
#define ROWS_PER_BLK (Cc / BPG)      // 32 channels reduced per block
#define F4_PER_BLK (Cc * N4 / BPG)   // 1568 float4 of x/out per block

// Zero-initialized device scratch (allocation-free rule). All counters/flags
// are restored to 0 by the phase-3 winner -> graph-replay deterministic.
__device__ float g_ysum[Bb * Cc];
__device__ float g_zbn[Bb * Cc];
__device__ int   g_cnt1[Bb];    // phase-1 arrivals per batch
__device__ int   g_cnt2[Bb];    // phase-3 arrivals per batch (winner resets all)
__device__ int   g_flag[Bb];    // zbn-ready flag per batch

// ---------------------------------------------------------------------------
// Single fused kernel. Math: softmax over a singleton axis == 1, so the
// attention collapses to a spatial sum (Wq, Wk dead):
//   zbn[b,:] = BN( Wz @ (Wv @ sum_n y[b,:,n]) )
//   out      = x + broadcast(zbn)
// ---------------------------------------------------------------------------
__global__ void __launch_bounds__(TPB)
k_all(const float* __restrict__ x,
      const float* __restrict__ y,
      const float* __restrict__ Wv,
      const float* __restrict__ Wz,
      const float* __restrict__ bn_w,
      const float* __restrict__ bn_b,
      const float* __restrict__ bn_m,
      const float* __restrict__ bn_v,
      float* __restrict__ out) {
    __shared__ float ys[Cc];
    __shared__ float tmp[CH];
    __shared__ float zloc[ROWS_PER_BLK];
    __shared__ int   s_winner;

    const int b    = blockIdx.x >> 3;     // batch
    const int g    = blockIdx.x & 7;      // sub-block within batch
    const int t    = threadIdx.x;
    const int warp = t >> 5;              // 0..7
    const int lane = t & 31;

    // ================= Phase 1: reduce 32 y-rows (4 rows/warp) =============
    {
        const int r0 = b * Cc + g * ROWS_PER_BLK + warp * 4;  // global row
        const float4* p0 = reinterpret_cast<const float4*>(y) + (size_t)r0 * N4;
        const float4* p1 = p0 + N4;
        const float4* p2 = p1 + N4;
        const float4* p3 = p2 + N4;
        const bool tail = (lane < N4 - 32);   // lanes 0..16 read the 17-f4 tail

        // 8 front-batched independent LDG.128 (MLP_p1 = 8)
        float4 a0 = p0[lane];
        float4 a1 = p1[lane];
        float4 a2 = p2[lane];
        float4 a3 = p3[lane];
        float4 t0 = tail ? p0[lane + 32] : make_float4(0,0,0,0);
        float4 t1 = tail ? p1[lane + 32] : make_float4(0,0,0,0);
        float4 t2 = tail ? p2[lane + 32] : make_float4(0,0,0,0);
        float4 t3 = tail ? p3[lane + 32] : make_float4(0,0,0,0);

        float s0 = a0.x+a0.y+a0.z+a0.w + t0.x+t0.y+t0.z+t0.w;
        float s1 = a1.x+a1.y+a1.z+a1.w + t1.x+t1.y+t1.z+t1.w;
        float s2 = a2.x+a2.y+a2.z+a2.w + t2.x+t2.y+t2.z+t2.w;
        float s3 = a3.x+a3.y+a3.z+a3.w + t3.x+t3.y+t3.z+t3.w;

        #pragma unroll
        for (int o = 16; o; o >>= 1) {   // 4 independent chains -> ILP
            s0 += __shfl_xor_sync(0xFFFFFFFFu, s0, o);
            s1 += __shfl_xor_sync(0xFFFFFFFFu, s1, o);
            s2 += __shfl_xor_sync(0xFFFFFFFFu, s2, o);
            s3 += __shfl_xor_sync(0xFFFFFFFFu, s3, o);
        }
        if (lane == 0) {
            g_ysum[r0]     = s0;
            g_ysum[r0 + 1] = s1;
            g_ysum[r0 + 2] = s2;
            g_ysum[r0 + 3] = s3;
        }
    }
    __threadfence();            // publish partial sums before arriving
    __syncthreads();

    if (t == 0) {
        int old = atomicAdd(&g_cnt1[b], 1);
        s_winner = (old == BPG - 1);
    }
    __syncthreads();

    // ================= Phase 2: winner computes zbn for batch b ============
    if (s_winner) {
        __threadfence();        // acquire siblings' g_ysum writes
        ys[t] = g_ysum[b * Cc + t];
        __syncthreads();

        // tmp[ch] = Wv[ch,:] . ys   (128 threads; others idle briefly)
        if (t < CH) {
            const float4* wr = reinterpret_cast<const float4*>(Wv + t * Cc);
            float acc = 0.0f;
            #pragma unroll
            for (int i = 0; i < Cc / 4; i++) {
                float4 v = wr[i];
                acc += v.x * ys[4*i]   + v.y * ys[4*i+1]
                     + v.z * ys[4*i+2] + v.w * ys[4*i+3];
            }
            tmp[t] = acc;
        }
        __syncthreads();

        // zbn[o] = BN( Wz[o,:] . tmp )   (256 threads)
        {
            const float4* wr = reinterpret_cast<const float4*>(Wz + t * CH);
            float acc = 0.0f;
            #pragma unroll
            for (int i = 0; i < CH / 4; i++) {
                float4 v = wr[i];
                acc += v.x * tmp[4*i]   + v.y * tmp[4*i+1]
                     + v.z * tmp[4*i+2] + v.w * tmp[4*i+3];
            }
            const float inv = rsqrtf(bn_v[t] + EPS);
            g_zbn[b * Cc + t] = (acc - bn_m[t]) * inv * bn_w[t] + bn_b[t];
        }
        __threadfence();        // publish zbn before raising flag
        __syncthreads();
        if (t == 0) atomicExch(&g_flag[b], 1);
    } else {
        // short spin: winner is a launch-adjacent sibling, wait ~proj time
        if (t == 0) {
            while (atomicAdd(&g_flag[b], 0) == 0) __nanosleep(64);
        }
        __syncthreads();
        __threadfence();        // acquire winner's zbn
    }

    // ================= Phase 3: stream out = x + zbn ========================
    // This block handles channels [g*32, g*32+32) of batch b:
    // exactly 1568 float4, channel = i / 49 within the slice.
    if (t < ROWS_PER_BLK) zloc[t] = g_zbn[b * Cc + g * ROWS_PER_BLK + t];
    __syncthreads();

    const size_t base = (size_t)b * (Cc * N4) + (size_t)g * F4_PER_BLK;
    const float4* X = reinterpret_cast<const float4*>(x) + base;
    float4*       O = reinterpret_cast<float4*>(out) + base;

    #pragma unroll
    for (int i = t; i < F4_PER_BLK; i += TPB) {
        const int ch = i / N4;          // 0..31
        const float z = zloc[ch];
        float4 v = X[i];
        v.x += z; v.y += z; v.z += z; v.w += z;
        O[i] = v;
    }

    // ================= Cleanup: last block resets batch state ==============
    __syncthreads();
    if (t == 0) {
        int old2 = atomicAdd(&g_cnt2[b], 1);
        if (old2 == BPG - 1) {          // graph-replay safe reset
            g_cnt1[b] = 0;
            g_flag[b] = 0;
            g_cnt2[b] = 0;
        }
    }
}

// ---------------------------------------------------------------------------
// Inputs (metadata order):
//  0:x 1:y 2:Wq 3:Wk 4:Wv 5:Wz 6:bn_weight 7:bn_bias 8:bn_mean 9:bn_var
// ---------------------------------------------------------------------------
extern "C" void kernel_launch(void* const* d_in, const int* in_sizes, int n_in,
                              void* d_out, int out_size) {
    const float* x    = (const float*)d_in[0];
    const float* y    = (const float*)d_in[1];
    const float* Wv   = (const float*)d_in[4];
    const float* Wz   = (const float*)d_in[5];
    const float* bn_w = (const float*)d_in[6];
    const float* bn_b = (const float*)d_in[7];
    const float* bn_m = (const float*)d_in[8];
    const float* bn_v = (const float*)d_in[9];
    float* out = (float*)d_out;

    k_all<<<GRID, TPB>>>(x, y, Wv, Wz, bn_w, bn_b, bn_m, bn_v, out);
}

// round 7
// speedup vs baseline: 1.3700x; 1.3700x over previous
#include <cuda_runtime.h>

// Shapes (fixed by the problem)
#define Bb 256
#define Cc 256
#define CH 128
#define NN 196               // H*W = 14*14
#define N4 49                // float4s per channel row
#define EPS 1e-5f

// K1: 2048 ysum blocks (32 rows each) + 64 weight-collapse blocks (4 rows each)
#define K1_YS_BLOCKS 2048
#define K1_WC_BLOCKS 64
#define K1_GRID (K1_YS_BLOCKS + K1_WC_BLOCKS)

// K2: 8 channel-slice blocks per batch
#define K2_GRID (Bb * 8)     // 2048

// Scratch (__device__ globals: allocation-free rule). All fully overwritten
// each launch -> graph-replay deterministic.
__device__ float g_ysum[Bb * Cc];    // per-(b,c) spatial sum of y
__device__ float g_wc[Cc * Cc];      // W' = diag(bn_scale) * (Wz @ Wv), row-major
__device__ float g_beta[Cc];         // beta' = bias - mean * bn_scale

// ---------------------------------------------------------------------------
// Math: softmax over a singleton axis == 1, so attention collapses to a
// spatial sum (Wq, Wk dead). Then:
//   zbn[b,o] = W'[o,:] . ysum[b,:] + beta'[o]
//   out      = x + broadcast(zbn)
// ---------------------------------------------------------------------------

// K1: two independent roles in one grid (no intra-kernel dependency).
__global__ void __launch_bounds__(256)
k1(const float* __restrict__ y,
   const float* __restrict__ Wv,
   const float* __restrict__ Wz,
   const float* __restrict__ bn_w,
   const float* __restrict__ bn_b,
   const float* __restrict__ bn_m,
   const float* __restrict__ bn_v) {
    const int t    = threadIdx.x;
    const int warp = t >> 5;
    const int lane = t & 31;

    if (blockIdx.x < K1_YS_BLOCKS) {
        // ---- role A: ysum. 8 warps x 4 adjacent rows, 8 front LDG.128 ----
        const int r0 = blockIdx.x * 32 + warp * 4;       // global (b,c) row
        const float4* p0 = reinterpret_cast<const float4*>(y) + (size_t)r0 * N4;
        const float4* p1 = p0 + N4;
        const float4* p2 = p1 + N4;
        const float4* p3 = p2 + N4;
        const bool tail = (lane < N4 - 32);              // lanes 0..16

        float4 a0 = p0[lane];
        float4 a1 = p1[lane];
        float4 a2 = p2[lane];
        float4 a3 = p3[lane];
        float4 t0 = tail ? p0[lane + 32] : make_float4(0,0,0,0);
        float4 t1 = tail ? p1[lane + 32] : make_float4(0,0,0,0);
        float4 t2 = tail ? p2[lane + 32] : make_float4(0,0,0,0);
        float4 t3 = tail ? p3[lane + 32] : make_float4(0,0,0,0);

        float s0 = a0.x+a0.y+a0.z+a0.w + t0.x+t0.y+t0.z+t0.w;
        float s1 = a1.x+a1.y+a1.z+a1.w + t1.x+t1.y+t1.z+t1.w;
        float s2 = a2.x+a2.y+a2.z+a2.w + t2.x+t2.y+t2.z+t2.w;
        float s3 = a3.x+a3.y+a3.z+a3.w + t3.x+t3.y+t3.z+t3.w;

        #pragma unroll
        for (int o = 16; o; o >>= 1) {
            s0 += __shfl_xor_sync(0xFFFFFFFFu, s0, o);
            s1 += __shfl_xor_sync(0xFFFFFFFFu, s1, o);
            s2 += __shfl_xor_sync(0xFFFFFFFFu, s2, o);
            s3 += __shfl_xor_sync(0xFFFFFFFFu, s3, o);
        }
        if (lane == 0)
            reinterpret_cast<float4*>(g_ysum)[r0 >> 2] =
                make_float4(s0, s1, s2, s3);
    } else {
        // ---- role B: W' = diag(s) * Wz @ Wv and beta'. 4 rows per block ----
        __shared__ float wzs[4][CH];
        __shared__ float ssc[4];
        const int o0 = (blockIdx.x - K1_YS_BLOCKS) * 4;  // output rows o0..o0+3

        // stage 4 Wz rows (512 floats, 256 threads x 2)
        #pragma unroll
        for (int j = 0; j < 2; j++) {
            const int e = j * 256 + t;
            wzs[e >> 7][e & 127] = Wz[(o0 + (e >> 7)) * CH + (e & 127)];
        }
        if (t < 4) {
            const int o = o0 + t;
            const float s = rsqrtf(bn_v[o] + EPS) * bn_w[o];
            ssc[t] = s;
            g_beta[o] = bn_b[o] - bn_m[o] * s;
        }
        __syncthreads();

        // column c = t: acc[r] = sum_k Wz[o0+r,k] * Wv[k,c]
        float acc0 = 0.f, acc1 = 0.f, acc2 = 0.f, acc3 = 0.f;
        #pragma unroll 4
        for (int k = 0; k < CH; k++) {
            const float v = Wv[k * Cc + t];              // coalesced
            acc0 += wzs[0][k] * v;                       // smem broadcast
            acc1 += wzs[1][k] * v;
            acc2 += wzs[2][k] * v;
            acc3 += wzs[3][k] * v;
        }
        g_wc[(o0 + 0) * Cc + t] = acc0 * ssc[0];
        g_wc[(o0 + 1) * Cc + t] = acc1 * ssc[1];
        g_wc[(o0 + 2) * Cc + t] = acc2 * ssc[2];
        g_wc[(o0 + 3) * Cc + t] = acc3 * ssc[3];
    }
}

// K2: block = (batch b, channel-slice g of 32 ch). Compute 32 zbn values,
// then stream out = x + zbn over the 32x196 slice.
__global__ void __launch_bounds__(256)
k2(const float* __restrict__ x, float* __restrict__ out) {
    __shared__ float zloc[32];
    const int b    = blockIdx.x >> 3;
    const int g    = blockIdx.x & 7;
    const int t    = threadIdx.x;
    const int warp = t >> 5;
    const int lane = t & 31;

    // ---- zbn for channels g*32..+32: 8 threads per channel ----
    {
        const int ch = t >> 3, part = t & 7;             // 32 ch x 8 parts
        const int o  = g * 32 + ch;
        // both reads fully coalesced: lanes of one ch-group span 8
        // consecutive float4 (128B); g_ysum slice is L1-hot across warps.
        const float4* wr = reinterpret_cast<const float4*>(g_wc) + o * (Cc/4) + part * 8;
        const float4* yr = reinterpret_cast<const float4*>(g_ysum) + b * (Cc/4) + part * 8;
        float acc = 0.0f;
        #pragma unroll
        for (int i = 0; i < 8; i++) {
            const float4 w = wr[i];
            const float4 v = yr[i];
            acc += w.x * v.x + w.y * v.y + w.z * v.z + w.w * v.w;
        }
        acc += __shfl_xor_sync(0xFFFFFFFFu, acc, 1);
        acc += __shfl_xor_sync(0xFFFFFFFFu, acc, 2);
        acc += __shfl_xor_sync(0xFFFFFFFFu, acc, 4);
        if (part == 0) zloc[ch] = acc + g_beta[o];
    }
    __syncthreads();

    // ---- stream 32 rows: 8 warps x 4 rows, 8 front-batched LDG.128 ----
    const int lr = warp * 4;                              // local row 0..28
    const size_t f4base = ((size_t)b * Cc + g * 32 + lr) * N4;
    const float4* X = reinterpret_cast<const float4*>(x) + f4base;
    float4*       O = reinterpret_cast<float4*>(out) + f4base;
    const bool tail = (lane < N4 - 32);

    float4 a0 = X[0*N4 + lane];
    float4 a1 = X[1*N4 + lane];
    float4 a2 = X[2*N4 + lane];
    float4 a3 = X[3*N4 + lane];
    float4 t0 = tail ? X[0*N4 + lane + 32] : make_float4(0,0,0,0);
    float4 t1 = tail ? X[1*N4 + lane + 32] : make_float4(0,0,0,0);
    float4 t2 = tail ? X[2*N4 + lane + 32] : make_float4(0,0,0,0);
    float4 t3 = tail ? X[3*N4 + lane + 32] : make_float4(0,0,0,0);

    const float z0 = zloc[lr + 0];
    const float z1 = zloc[lr + 1];
    const float z2 = zloc[lr + 2];
    const float z3 = zloc[lr + 3];

    a0.x += z0; a0.y += z0; a0.z += z0; a0.w += z0;
    a1.x += z1; a1.y += z1; a1.z += z1; a1.w += z1;
    a2.x += z2; a2.y += z2; a2.z += z2; a2.w += z2;
    a3.x += z3; a3.y += z3; a3.z += z3; a3.w += z3;
    O[0*N4 + lane] = a0;
    O[1*N4 + lane] = a1;
    O[2*N4 + lane] = a2;
    O[3*N4 + lane] = a3;

    if (tail) {
        t0.x += z0; t0.y += z0; t0.z += z0; t0.w += z0;
        t1.x += z1; t1.y += z1; t1.z += z1; t1.w += z1;
        t2.x += z2; t2.y += z2; t2.z += z2; t2.w += z2;
        t3.x += z3; t3.y += z3; t3.z += z3; t3.w += z3;
        O[0*N4 + lane + 32] = t0;
        O[1*N4 + lane + 32] = t1;
        O[2*N4 + lane + 32] = t2;
        O[3*N4 + lane + 32] = t3;
    }
}

// ---------------------------------------------------------------------------
// Inputs (metadata order):
//  0:x 1:y 2:Wq 3:Wk 4:Wv 5:Wz 6:bn_weight 7:bn_bias 8:bn_mean 9:bn_var
// ---------------------------------------------------------------------------
extern "C" void kernel_launch(void* const* d_in, const int* in_sizes, int n_in,
                              void* d_out, int out_size) {
    const float* x    = (const float*)d_in[0];
    const float* y    = (const float*)d_in[1];
    const float* Wv   = (const float*)d_in[4];
    const float* Wz   = (const float*)d_in[5];
    const float* bn_w = (const float*)d_in[6];
    const float* bn_b = (const float*)d_in[7];
    const float* bn_m = (const float*)d_in[8];
    const float* bn_v = (const float*)d_in[9];
    float* out = (float*)d_out;

    k1<<<K1_GRID, 256>>>(y, Wv, Wz, bn_w, bn_b, bn_m, bn_v);
    k2<<<K2_GRID, 256>>>(x, out);
}

// round 8
// speedup vs baseline: 1.9711x; 1.4387x over previous
#include <cuda_runtime.h>

// Shapes (fixed by the problem)
#define Bb 256
#define Cc 256
#define CH 128
#define NN 196               // H*W = 14*14
#define N4 49                // float4s per channel row
#define EPS 1e-5f

// K1: 64 weight-collapse blocks FIRST (hide their latency under the stream),
// then 2048 ysum blocks (32 rows each).
#define K1_WC_BLOCKS 64
#define K1_GRID (K1_WC_BLOCKS + 2048)

// K3: exact tiling, 1568 * 512 * 4 f4 = 3,211,264 = Bb*Cc*N4
#define K3_BLOCKS 1568
#define K3_THREADS 512
#define K3_STRIDE (K3_BLOCKS * K3_THREADS)

// Scratch (__device__ globals; fully overwritten per launch -> replay-safe)
__device__ float g_ysum[Bb * Cc];    // per-(b,c) spatial sum of y
__device__ float g_wcT[Cc * Cc];     // W'^T: [c][o], W' = diag(s)*(Wz@Wv)
__device__ float g_beta[Cc];         // beta' = bias - mean*s
__device__ float g_zbn[Bb * Cc];     // BN-folded additive term

// ---------------------------------------------------------------------------
// Math: softmax over a singleton axis == 1 -> attention collapses to the
// spatial sum (Wq, Wk dead):
//   zbn[b,o] = sum_c W'[o,c]*ysum[b,c] + beta'[o];  out = x + bcast(zbn)
// ---------------------------------------------------------------------------

// K1: two independent roles, no intra-kernel dependency.
__global__ void __launch_bounds__(256)
k1(const float* __restrict__ y,
   const float* __restrict__ Wv,
   const float* __restrict__ Wz,
   const float* __restrict__ bn_w,
   const float* __restrict__ bn_b,
   const float* __restrict__ bn_m,
   const float* __restrict__ bn_v) {
    const int t    = threadIdx.x;
    const int warp = t >> 5;
    const int lane = t & 31;

    if (blockIdx.x >= K1_WC_BLOCKS) {
        // ---- role A: ysum. 8 warps x 4 adjacent rows, 8 front LDG.128 ----
        const int r0 = (blockIdx.x - K1_WC_BLOCKS) * 32 + warp * 4;
        const float4* p0 = reinterpret_cast<const float4*>(y) + (size_t)r0 * N4;
        const float4* p1 = p0 + N4;
        const float4* p2 = p1 + N4;
        const float4* p3 = p2 + N4;
        const bool tail = (lane < N4 - 32);              // lanes 0..16

        float4 a0 = p0[lane];
        float4 a1 = p1[lane];
        float4 a2 = p2[lane];
        float4 a3 = p3[lane];
        float4 t0 = tail ? p0[lane + 32] : make_float4(0,0,0,0);
        float4 t1 = tail ? p1[lane + 32] : make_float4(0,0,0,0);
        float4 t2 = tail ? p2[lane + 32] : make_float4(0,0,0,0);
        float4 t3 = tail ? p3[lane + 32] : make_float4(0,0,0,0);

        float s0 = a0.x+a0.y+a0.z+a0.w + t0.x+t0.y+t0.z+t0.w;
        float s1 = a1.x+a1.y+a1.z+a1.w + t1.x+t1.y+t1.z+t1.w;
        float s2 = a2.x+a2.y+a2.z+a2.w + t2.x+t2.y+t2.z+t2.w;
        float s3 = a3.x+a3.y+a3.z+a3.w + t3.x+t3.y+t3.z+t3.w;

        #pragma unroll
        for (int o = 16; o; o >>= 1) {
            s0 += __shfl_xor_sync(0xFFFFFFFFu, s0, o);
            s1 += __shfl_xor_sync(0xFFFFFFFFu, s1, o);
            s2 += __shfl_xor_sync(0xFFFFFFFFu, s2, o);
            s3 += __shfl_xor_sync(0xFFFFFFFFu, s3, o);
        }
        if (lane == 0)
            reinterpret_cast<float4*>(g_ysum)[r0 >> 2] =
                make_float4(s0, s1, s2, s3);
    } else {
        // ---- role B: W'^T[c][o] = s[o] * sum_k Wz[o,k]*Wv[k,c], beta' ----
        __shared__ float wzs[4][CH];
        __shared__ float ssc[4];
        const int o0 = blockIdx.x * 4;                   // output rows o0..o0+3

        #pragma unroll
        for (int j = 0; j < 2; j++) {                    // stage 4 Wz rows
            const int e = j * 256 + t;
            wzs[e >> 7][e & 127] = Wz[(o0 + (e >> 7)) * CH + (e & 127)];
        }
        if (t < 4) {
            const int o = o0 + t;
            const float s = rsqrtf(bn_v[o] + EPS) * bn_w[o];
            ssc[t] = s;
            g_beta[o] = bn_b[o] - bn_m[o] * s;
        }
        __syncthreads();

        // column c = t: coalesced Wv reads, smem-broadcast Wz
        float acc0 = 0.f, acc1 = 0.f, acc2 = 0.f, acc3 = 0.f;
        #pragma unroll 8
        for (int k = 0; k < CH; k++) {
            const float v = Wv[k * Cc + t];
            acc0 += wzs[0][k] * v;
            acc1 += wzs[1][k] * v;
            acc2 += wzs[2][k] * v;
            acc3 += wzs[3][k] * v;
        }
        // transposed store (scattered but tiny; STG is fire-and-forget)
        g_wcT[t * Cc + o0 + 0] = acc0 * ssc[0];
        g_wcT[t * Cc + o0 + 1] = acc1 * ssc[1];
        g_wcT[t * Cc + o0 + 2] = acc2 * ssc[2];
        g_wcT[t * Cc + o0 + 3] = acc3 * ssc[3];
    }
}

// K2: zbn[b,o] = sum_c ysum[b,c] * W'^T[c,o] + beta'[o].
// Grid 128 x 512: block = 2 batches; thread (part,o) with o = t&255 ->
// g_wcT reads perfectly coalesced; 2-way c-split halves the serial chain.
__global__ void __launch_bounds__(512)
k2(int dummy) {
    __shared__ float ys2[2][Cc];
    __shared__ float pacc[2][Cc];
    const int b0   = blockIdx.x * 2;
    const int t    = threadIdx.x;
    const int part = t >> 8;         // 0 or 1
    const int o    = t & 255;

    ys2[part][o] = g_ysum[(b0 + part) * Cc + o];   // 512 coalesced loads
    __syncthreads();

    const int c0 = part * 128;
    float acc0 = 0.f, acc1 = 0.f;
    #pragma unroll 8
    for (int c = c0; c < c0 + 128; c++) {
        const float w = g_wcT[c * Cc + o];         // coalesced across o
        acc0 += ys2[0][c] * w;
        acc1 += ys2[1][c] * w;
    }
    if (part == 1) { pacc[0][o] = acc0; pacc[1][o] = acc1; }
    __syncthreads();
    if (part == 0) {
        const float be = g_beta[o];
        g_zbn[(b0 + 0) * Cc + o] = acc0 + pacc[0][o] + be;
        g_zbn[(b0 + 1) * Cc + o] = acc1 + pacc[1][o] + be;
    }
}

// K3: out[i] = x[i] + zbn[i / 49] over float4s (measured 15.2us shape).
__global__ void __launch_bounds__(K3_THREADS)
k3(const float* __restrict__ x, float* __restrict__ out) {
    const int tid = blockIdx.x * K3_THREADS + threadIdx.x;
    const float4* x4 = reinterpret_cast<const float4*>(x);
    float4*       o4 = reinterpret_cast<float4*>(out);

    float4 v0 = x4[tid + 0 * K3_STRIDE];
    float4 v1 = x4[tid + 1 * K3_STRIDE];
    float4 v2 = x4[tid + 2 * K3_STRIDE];
    float4 v3 = x4[tid + 3 * K3_STRIDE];

    const float z0 = __ldg(&g_zbn[(tid + 0 * K3_STRIDE) / N4]);
    const float z1 = __ldg(&g_zbn[(tid + 1 * K3_STRIDE) / N4]);
    const float z2 = __ldg(&g_zbn[(tid + 2 * K3_STRIDE) / N4]);
    const float z3 = __ldg(&g_zbn[(tid + 3 * K3_STRIDE) / N4]);

    v0.x += z0; v0.y += z0; v0.z += z0; v0.w += z0;
    v1.x += z1; v1.y += z1; v1.z += z1; v1.w += z1;
    v2.x += z2; v2.y += z2; v2.z += z2; v2.w += z2;
    v3.x += z3; v3.y += z3; v3.z += z3; v3.w += z3;

    o4[tid + 0 * K3_STRIDE] = v0;
    o4[tid + 1 * K3_STRIDE] = v1;
    o4[tid + 2 * K3_STRIDE] = v2;
    o4[tid + 3 * K3_STRIDE] = v3;
}

// ---------------------------------------------------------------------------
// Inputs (metadata order):
//  0:x 1:y 2:Wq 3:Wk 4:Wv 5:Wz 6:bn_weight 7:bn_bias 8:bn_mean 9:bn_var
// ---------------------------------------------------------------------------
extern "C" void kernel_launch(void* const* d_in, const int* in_sizes, int n_in,
                              void* d_out, int out_size) {
    const float* x    = (const float*)d_in[0];
    const float* y    = (const float*)d_in[1];
    const float* Wv   = (const float*)d_in[4];
    const float* Wz   = (const float*)d_in[5];
    const float* bn_w = (const float*)d_in[6];
    const float* bn_b = (const float*)d_in[7];
    const float* bn_m = (const float*)d_in[8];
    const float* bn_v = (const float*)d_in[9];
    float* out = (float*)d_out;

    k1<<<K1_GRID, 256>>>(y, Wv, Wz, bn_w, bn_b, bn_m, bn_v);
    k2<<<Bb / 2, 512>>>(0);
    k3<<<K3_BLOCKS, K3_THREADS>>>(x, out);
}

// round 9
// speedup vs baseline: 2.2496x; 1.1413x over previous
#include <cuda_runtime.h>

// Shapes (fixed by the problem)
#define Bb 256
#define Cc 256
#define CH 128
#define NN 196               // H*W = 14*14
#define N4 49                // float4s per channel row
#define EPS 1e-5f

// K2: 32 blocks x 512 thr, 8 batches per block
#define K2_BLOCKS 32
#define K2_BPB 8

// K3: exact tiling, 1568 * 512 * 4 f4 = 3,211,264 = Bb*Cc*N4
#define K3_BLOCKS 1568
#define K3_THREADS 512
#define K3_STRIDE (K3_BLOCKS * K3_THREADS)

// Scratch (__device__ globals; fully overwritten per launch -> replay-safe)
__device__ float g_ysum[Bb * Cc];    // per-(b,c) spatial sum of y
__device__ float g_zbn[Bb * Cc];     // BN-folded additive term

// ---------------------------------------------------------------------------
// Math: softmax over a singleton axis == 1 -> attention collapses to the
// spatial sum (Wq, Wk dead):
//   zbn[b,o] = BN( Wz[o,:] @ (Wv @ ysum[b,:]) );  out = x + bcast(zbn)
// ---------------------------------------------------------------------------

// K1: ysum. One warp per 2 adjacent rows, 4 front-batched LDG.128.
// (R5-measured: 11.5us, 57% DRAM, regs 24.)
__global__ void __launch_bounds__(256)
k_ysum(const float* __restrict__ y) {
    const int gw   = (blockIdx.x * 256 + threadIdx.x) >> 5;  // global warp
    const int lane = threadIdx.x & 31;
    const int row0 = gw * 2;

    const float4* r0 = reinterpret_cast<const float4*>(y) + (size_t)row0 * N4;
    const float4* r1 = r0 + N4;

    float4 a0 = r0[lane];
    float4 a1 = (lane < N4 - 32) ? r0[lane + 32] : make_float4(0,0,0,0);
    float4 b0 = r1[lane];
    float4 b1 = (lane < N4 - 32) ? r1[lane + 32] : make_float4(0,0,0,0);

    float s0 = a0.x + a0.y + a0.z + a0.w + a1.x + a1.y + a1.z + a1.w;
    float s1 = b0.x + b0.y + b0.z + b0.w + b1.x + b1.y + b1.z + b1.w;
    #pragma unroll
    for (int o = 16; o; o >>= 1) {
        s0 += __shfl_xor_sync(0xFFFFFFFFu, s0, o);
        s1 += __shfl_xor_sync(0xFFFFFFFFu, s1, o);
    }
    if (lane == 0) g_ysum[row0]     = s0;
    if (lane == 1) g_ysum[row0 + 1] = s1;
}

// K2: fused two-stage projection for 8 batches per block.
__global__ void __launch_bounds__(512)
k_proj(const float* __restrict__ Wv,
       const float* __restrict__ Wz,
       const float* __restrict__ bn_w,
       const float* __restrict__ bn_b,
       const float* __restrict__ bn_m,
       const float* __restrict__ bn_v) {
    __shared__ float ys[K2_BPB * Cc];    // [b][c]   8 KB
    __shared__ float tmp[K2_BPB * CH];   // [b][ch]  4 KB

    const int b0 = blockIdx.x * K2_BPB;
    const int t  = threadIdx.x;

    // stage ysum for 8 batches (2048 floats, coalesced)
    #pragma unroll
    for (int j = 0; j < 4; j++) {
        const int idx = j * 512 + t;
        ys[idx] = g_ysum[b0 * Cc + idx];
    }
    __syncthreads();

    // ---- Phase A: tmp[b][ch] = Wv[ch,:] . ys[b,:]  (128 ch x 4 parts) ----
    {
        const int ch = t >> 2, part = t & 3;
        const float4* wv4 = reinterpret_cast<const float4*>(Wv + ch * Cc);
        float acc[K2_BPB];
        #pragma unroll
        for (int b = 0; b < K2_BPB; b++) acc[b] = 0.0f;

        #pragma unroll
        for (int i = 0; i < 16; i++) {
            const int f4i = part + 4 * i;        // parts contiguous -> 64B runs
            const float4 w = wv4[f4i];
            const int cf = f4i * 4;
            #pragma unroll
            for (int b = 0; b < K2_BPB; b++) {
                const float* yb = ys + b * Cc + cf;
                acc[b] += w.x * yb[0] + w.y * yb[1] + w.z * yb[2] + w.w * yb[3];
            }
        }
        #pragma unroll
        for (int b = 0; b < K2_BPB; b++) {
            acc[b] += __shfl_xor_sync(0xFFFFFFFFu, acc[b], 1);
            acc[b] += __shfl_xor_sync(0xFFFFFFFFu, acc[b], 2);
        }
        if (part == 0) {
            #pragma unroll
            for (int b = 0; b < K2_BPB; b++) tmp[b * CH + ch] = acc[b];
        }
    }
    __syncthreads();

    // ---- Phase B: zbn[b][o] = BN( Wz[o,:] . tmp[b,:] )  (256 o x 2 parts) --
    {
        const int o = t >> 1, p2 = t & 1;
        const float4* wz4 = reinterpret_cast<const float4*>(Wz + o * CH);
        float acc[K2_BPB];
        #pragma unroll
        for (int b = 0; b < K2_BPB; b++) acc[b] = 0.0f;

        #pragma unroll
        for (int i = 0; i < 16; i++) {
            const int f4i = p2 + 2 * i;
            const float4 w = wz4[f4i];
            const int cf = f4i * 4;
            #pragma unroll
            for (int b = 0; b < K2_BPB; b++) {
                const float* tb = tmp + b * CH + cf;
                acc[b] += w.x * tb[0] + w.y * tb[1] + w.z * tb[2] + w.w * tb[3];
            }
        }
        #pragma unroll
        for (int b = 0; b < K2_BPB; b++)
            acc[b] += __shfl_xor_sync(0xFFFFFFFFu, acc[b], 1);

        if (p2 == 0) {
            const float s  = rsqrtf(bn_v[o] + EPS) * bn_w[o];
            const float be = bn_b[o] - bn_m[o] * s;
            #pragma unroll
            for (int b = 0; b < K2_BPB; b++)
                g_zbn[(b0 + b) * Cc + o] = acc[b] * s + be;
        }
    }
}

// K3: out[i] = x[i] + zbn[i / 49] over float4s (measured 15.2us shape).
__global__ void __launch_bounds__(K3_THREADS)
k_out(const float* __restrict__ x, float* __restrict__ out) {
    const int tid = blockIdx.x * K3_THREADS + threadIdx.x;
    const float4* x4 = reinterpret_cast<const float4*>(x);
    float4*       o4 = reinterpret_cast<float4*>(out);

    float4 v0 = x4[tid + 0 * K3_STRIDE];
    float4 v1 = x4[tid + 1 * K3_STRIDE];
    float4 v2 = x4[tid + 2 * K3_STRIDE];
    float4 v3 = x4[tid + 3 * K3_STRIDE];

    const float z0 = __ldg(&g_zbn[(tid + 0 * K3_STRIDE) / N4]);
    const float z1 = __ldg(&g_zbn[(tid + 1 * K3_STRIDE) / N4]);
    const float z2 = __ldg(&g_zbn[(tid + 2 * K3_STRIDE) / N4]);
    const float z3 = __ldg(&g_zbn[(tid + 3 * K3_STRIDE) / N4]);

    v0.x += z0; v0.y += z0; v0.z += z0; v0.w += z0;
    v1.x += z1; v1.y += z1; v1.z += z1; v1.w += z1;
    v2.x += z2; v2.y += z2; v2.z += z2; v2.w += z2;
    v3.x += z3; v3.y += z3; v3.z += z3; v3.w += z3;

    o4[tid + 0 * K3_STRIDE] = v0;
    o4[tid + 1 * K3_STRIDE] = v1;
    o4[tid + 2 * K3_STRIDE] = v2;
    o4[tid + 3 * K3_STRIDE] = v3;
}

// ---------------------------------------------------------------------------
// Inputs (metadata order):
//  0:x 1:y 2:Wq 3:Wk 4:Wv 5:Wz 6:bn_weight 7:bn_bias 8:bn_mean 9:bn_var
// ---------------------------------------------------------------------------
extern "C" void kernel_launch(void* const* d_in, const int* in_sizes, int n_in,
                              void* d_out, int out_size) {
    const float* x    = (const float*)d_in[0];
    const float* y    = (const float*)d_in[1];
    const float* Wv   = (const float*)d_in[4];
    const float* Wz   = (const float*)d_in[5];
    const float* bn_w = (const float*)d_in[6];
    const float* bn_b = (const float*)d_in[7];
    const float* bn_m = (const float*)d_in[8];
    const float* bn_v = (const float*)d_in[9];
    float* out = (float*)d_out;

    k_ysum<<<4096, 256>>>(y);
    k_proj<<<K2_BLOCKS, 512>>>(Wv, Wz, bn_w, bn_b, bn_m, bn_v);
    k_out<<<K3_BLOCKS, K3_THREADS>>>(x, out);
}

// round 10
// speedup vs baseline: 2.5824x; 1.1479x over previous
#include <cuda_runtime.h>

// Shapes (fixed by the problem)
#define Bb 256
#define Cc 256
#define CH 128
#define NN 196               // H*W = 14*14
#define N4 49                // float4s per channel row
#define EPS 1e-5f

#define K1_GRID 2048         // block = (batch, 32-channel slice)
#define K2_GRID 2048         // block = (batch, 32-channel slice)

// Scratch (__device__ globals; fully overwritten per launch -> replay-safe)
// g_tmp_part[bid][ch]: partial of tmp[b,ch] = (Wv @ ysum[b])[ch] from slice grp.
__device__ float g_tmp_part[K1_GRID * CH];   // 1 MB

// ---------------------------------------------------------------------------
// Math: softmax over a singleton axis == 1 -> attention collapses to the
// spatial sum (Wq, Wk dead):
//   tmp[b]   = Wv @ (sum_n y[b,:,n])
//   zbn[b,o] = BN( Wz[o,:] . tmp[b] );   out = x + bcast(zbn)
// tmp distributes over 32-channel slices -> no cross-block dependency in K1.
// ---------------------------------------------------------------------------

// K1: block bid covers global rows [bid*32, bid*32+32) (batch b=bid>>3,
// slice grp=bid&7). 16 warps x 2 rows (R5-proven stream), then the Wv-slice
// partial projection (tiny, L2-resident).
__global__ void __launch_bounds__(512)
k1(const float* __restrict__ y, const float* __restrict__ Wv) {
    __shared__ float ys_s[32];
    const int bid  = blockIdx.x;
    const int t    = threadIdx.x;
    const int warp = t >> 5;
    const int lane = t & 31;

    // ---- stream: 2 adjacent rows per warp, 4 front-batched LDG.128 ----
    const int r0 = bid * 32 + warp * 2;
    const float4* p0 = reinterpret_cast<const float4*>(y) + (size_t)r0 * N4;
    const float4* p1 = p0 + N4;

    float4 a0 = p0[lane];
    float4 a1 = (lane < N4 - 32) ? p0[lane + 32] : make_float4(0,0,0,0);
    float4 b0 = p1[lane];
    float4 b1 = (lane < N4 - 32) ? p1[lane + 32] : make_float4(0,0,0,0);

    float s0 = a0.x + a0.y + a0.z + a0.w + a1.x + a1.y + a1.z + a1.w;
    float s1 = b0.x + b0.y + b0.z + b0.w + b1.x + b1.y + b1.z + b1.w;
    #pragma unroll
    for (int o = 16; o; o >>= 1) {
        s0 += __shfl_xor_sync(0xFFFFFFFFu, s0, o);
        s1 += __shfl_xor_sync(0xFFFFFFFFu, s1, o);
    }
    if (lane == 0) { ys_s[warp * 2] = s0; ys_s[warp * 2 + 1] = s1; }
    __syncthreads();

    // ---- partial projection: p[ch] = sum_{j<32} Wv[ch, grp*32+j]*ys_s[j] ----
    // 512 thr = 128 ch x 4 parts; each thread 2 float4 of Wv (32B contiguous).
    {
        const int ch = t >> 2, part = t & 3;
        const int grp = bid & 7;
        const float4* wv4 = reinterpret_cast<const float4*>(Wv)
                          + ch * (Cc / 4) + grp * 8 + part * 2;
        float acc = 0.0f;
        #pragma unroll
        for (int i = 0; i < 2; i++) {
            const float4 w = wv4[i];
            const float* yy = ys_s + (part * 2 + i) * 4;
            acc += w.x * yy[0] + w.y * yy[1] + w.z * yy[2] + w.w * yy[3];
        }
        acc += __shfl_xor_sync(0xFFFFFFFFu, acc, 1);
        acc += __shfl_xor_sync(0xFFFFFFFFu, acc, 2);
        if (part == 0) g_tmp_part[bid * CH + ch] = acc;   // coalesced
    }
}

// K2: block bid = (batch b=bid>>3, slice grp=bid&7).
//  1) tmp[b] = fixed-order sum of the 8 slice partials (deterministic)
//  2) zbn for this block's 32 channels via coalesced Wz rows
//  3) stream out = x + zbn over the 32x196 slice (8 warps x 4 rows)
__global__ void __launch_bounds__(256)
k2(const float* __restrict__ x,
   const float* __restrict__ Wz,
   const float* __restrict__ bn_w,
   const float* __restrict__ bn_b,
   const float* __restrict__ bn_m,
   const float* __restrict__ bn_v,
   float* __restrict__ out) {
    __shared__ __align__(16) float tmp_s[CH];
    __shared__ float zloc[32];
    const int bid  = blockIdx.x;
    const int t    = threadIdx.x;
    const int warp = t >> 5;
    const int lane = t & 31;

    // ---- 1) reduce the 8 partials (fixed order -> deterministic) ----
    if (t < CH) {
        const int b = bid >> 3;
        float a = 0.0f;
        #pragma unroll
        for (int g = 0; g < 8; g++)
            a += g_tmp_part[(b * 8 + g) * CH + t];       // coalesced
        tmp_s[t] = a;
    }
    __syncthreads();

    // ---- 2) zbn: 32 ch x 8 parts; Wz rows read 64B/thread contiguous ----
    {
        const int och = t >> 3, part = t & 7;
        const int o   = (bid & 7) * 32 + och;
        const float4* wz4 = reinterpret_cast<const float4*>(Wz)
                          + o * (CH / 4) + part * 4;
        const float4* tp4 = reinterpret_cast<const float4*>(tmp_s) + part * 4;
        float acc = 0.0f;
        #pragma unroll
        for (int i = 0; i < 4; i++) {
            const float4 w = wz4[i];
            const float4 v = tp4[i];
            acc += w.x * v.x + w.y * v.y + w.z * v.z + w.w * v.w;
        }
        acc += __shfl_xor_sync(0xFFFFFFFFu, acc, 1);
        acc += __shfl_xor_sync(0xFFFFFFFFu, acc, 2);
        acc += __shfl_xor_sync(0xFFFFFFFFu, acc, 4);
        if (part == 0) {
            const float s = rsqrtf(bn_v[o] + EPS) * bn_w[o];
            zloc[och] = acc * s + bn_b[o] - bn_m[o] * s;
        }
    }
    __syncthreads();

    // ---- 3) stream 32 rows: 8 warps x 4 rows, 8 front-batched LDG.128 ----
    const int lr = warp * 4;
    const size_t f4base = ((size_t)bid * 32 + lr) * N4;
    const float4* X = reinterpret_cast<const float4*>(x) + f4base;
    float4*       O = reinterpret_cast<float4*>(out) + f4base;
    const bool tail = (lane < N4 - 32);

    float4 a0 = X[0*N4 + lane];
    float4 a1 = X[1*N4 + lane];
    float4 a2 = X[2*N4 + lane];
    float4 a3 = X[3*N4 + lane];
    float4 t0 = tail ? X[0*N4 + lane + 32] : make_float4(0,0,0,0);
    float4 t1 = tail ? X[1*N4 + lane + 32] : make_float4(0,0,0,0);
    float4 t2 = tail ? X[2*N4 + lane + 32] : make_float4(0,0,0,0);
    float4 t3 = tail ? X[3*N4 + lane + 32] : make_float4(0,0,0,0);

    const float z0 = zloc[lr + 0];
    const float z1 = zloc[lr + 1];
    const float z2 = zloc[lr + 2];
    const float z3 = zloc[lr + 3];

    a0.x += z0; a0.y += z0; a0.z += z0; a0.w += z0;
    a1.x += z1; a1.y += z1; a1.z += z1; a1.w += z1;
    a2.x += z2; a2.y += z2; a2.z += z2; a2.w += z2;
    a3.x += z3; a3.y += z3; a3.z += z3; a3.w += z3;
    O[0*N4 + lane] = a0;
    O[1*N4 + lane] = a1;
    O[2*N4 + lane] = a2;
    O[3*N4 + lane] = a3;

    if (tail) {
        t0.x += z0; t0.y += z0; t0.z += z0; t0.w += z0;
        t1.x += z1; t1.y += z1; t1.z += z1; t1.w += z1;
        t2.x += z2; t2.y += z2; t2.z += z2; t2.w += z2;
        t3.x += z3; t3.y += z3; t3.z += z3; t3.w += z3;
        O[0*N4 + lane + 32] = t0;
        O[1*N4 + lane + 32] = t1;
        O[2*N4 + lane + 32] = t2;
        O[3*N4 + lane + 32] = t3;
    }
}

// ---------------------------------------------------------------------------
// Inputs (metadata order):
//  0:x 1:y 2:Wq 3:Wk 4:Wv 5:Wz 6:bn_weight 7:bn_bias 8:bn_mean 9:bn_var
// ---------------------------------------------------------------------------
extern "C" void kernel_launch(void* const* d_in, const int* in_sizes, int n_in,
                              void* d_out, int out_size) {
    const float* x    = (const float*)d_in[0];
    const float* y    = (const float*)d_in[1];
    const float* Wv   = (const float*)d_in[4];
    const float* Wz   = (const float*)d_in[5];
    const float* bn_w = (const float*)d_in[6];
    const float* bn_b = (const float*)d_in[7];
    const float* bn_m = (const float*)d_in[8];
    const float* bn_v = (const float*)d_in[9];
    float* out = (float*)d_out;

    k1<<<K1_GRID, 512>>>(y, Wv);
    k2<<<K2_GRID, 256>>>(x, Wz, bn_w, bn_b, bn_m, bn_v, out);
}

// round 11
// speedup vs baseline: 2.9548x; 1.1442x over previous
#include <cuda_runtime.h>

// Shapes (fixed by the problem)
#define Bb 256
#define Cc 256
#define CH 128
#define NN 196               // H*W = 14*14
#define N4 49                // float4s per channel row
#define EPS 1e-5f

#define K1_GRID 2048         // block = (batch, 32-channel slice)
#define K2_GRID 2048         // block = (batch, 32-channel slice)

// Scratch (__device__ globals; fully overwritten per launch -> replay-safe)
// g_tmp_part[bid][ch]: partial of tmp[b,ch] = (Wv @ ysum[b])[ch] from slice grp.
__device__ float g_tmp_part[K1_GRID * CH];   // 1 MB

// ---------------------------------------------------------------------------
// Math: softmax over a singleton axis == 1 -> attention collapses to the
// spatial sum (Wq, Wk dead):
//   tmp[b]   = Wv @ (sum_n y[b,:,n])
//   zbn[b,o] = BN( Wz[o,:] . tmp[b] );   out = x + bcast(zbn)
// tmp distributes over 32-channel slices -> no cross-block dependency in K1.
// ---------------------------------------------------------------------------

// K1: block bid covers global rows [bid*32, bid*32+32). 16 warps x 2 rows
// (proven stream shape), then the Wv-slice partial projection (L2-resident).
__global__ void __launch_bounds__(512)
k1(const float* __restrict__ y, const float* __restrict__ Wv) {
    __shared__ float ys_s[32];
    const int bid  = blockIdx.x;
    const int t    = threadIdx.x;
    const int warp = t >> 5;
    const int lane = t & 31;

    // ---- stream: 2 adjacent rows per warp, 4 front-batched LDG.128 ----
    const int r0 = bid * 32 + warp * 2;
    const float4* p0 = reinterpret_cast<const float4*>(y) + (size_t)r0 * N4;
    const float4* p1 = p0 + N4;

    float4 a0 = p0[lane];
    float4 a1 = (lane < N4 - 32) ? p0[lane + 32] : make_float4(0,0,0,0);
    float4 b0 = p1[lane];
    float4 b1 = (lane < N4 - 32) ? p1[lane + 32] : make_float4(0,0,0,0);

    float s0 = a0.x + a0.y + a0.z + a0.w + a1.x + a1.y + a1.z + a1.w;
    float s1 = b0.x + b0.y + b0.z + b0.w + b1.x + b1.y + b1.z + b1.w;
    #pragma unroll
    for (int o = 16; o; o >>= 1) {
        s0 += __shfl_xor_sync(0xFFFFFFFFu, s0, o);
        s1 += __shfl_xor_sync(0xFFFFFFFFu, s1, o);
    }
    if (lane == 0) { ys_s[warp * 2] = s0; ys_s[warp * 2 + 1] = s1; }
    __syncthreads();

    // ---- partial projection: p[ch] = sum_{j<32} Wv[ch, grp*32+j]*ys_s[j] ----
    {
        const int ch = t >> 2, part = t & 3;
        const int grp = bid & 7;
        const float4* wv4 = reinterpret_cast<const float4*>(Wv)
                          + ch * (Cc / 4) + grp * 8 + part * 2;
        float acc = 0.0f;
        #pragma unroll
        for (int i = 0; i < 2; i++) {
            const float4 w = wv4[i];
            const float* yy = ys_s + (part * 2 + i) * 4;
            acc += w.x * yy[0] + w.y * yy[1] + w.z * yy[2] + w.w * yy[3];
        }
        acc += __shfl_xor_sync(0xFFFFFFFFu, acc, 1);
        acc += __shfl_xor_sync(0xFFFFFFFFu, acc, 2);
        if (part == 0) g_tmp_part[bid * CH + ch] = acc;   // coalesced
    }
}

// K2: block bid = (batch b=bid>>3, slice grp=bid&7).
// NEW ORDER: front-batch the 8 x LDG.128 FIRST, run the zbn preamble while
// they are in flight, then add + store. DRAM stays fed from cycle 0.
__global__ void __launch_bounds__(256)
k2(const float* __restrict__ x,
   const float* __restrict__ Wz,
   const float* __restrict__ bn_w,
   const float* __restrict__ bn_b,
   const float* __restrict__ bn_m,
   const float* __restrict__ bn_v,
   float* __restrict__ out) {
    __shared__ __align__(16) float tmp_s[CH];
    __shared__ float zloc[32];
    const int bid  = blockIdx.x;
    const int t    = threadIdx.x;
    const int warp = t >> 5;
    const int lane = t & 31;

    // ---- 0) front-batched x loads (8 independent LDG.128 per thread) ----
    const int lr = warp * 4;                            // local rows lr..lr+3
    const size_t f4base = ((size_t)bid * 32 + lr) * N4;
    const float4* X = reinterpret_cast<const float4*>(x) + f4base;
    float4*       O = reinterpret_cast<float4*>(out) + f4base;
    const bool tail = (lane < N4 - 32);

    float4 a0 = X[0*N4 + lane];
    float4 a1 = X[1*N4 + lane];
    float4 a2 = X[2*N4 + lane];
    float4 a3 = X[3*N4 + lane];
    float4 t0 = tail ? X[0*N4 + lane + 32] : make_float4(0,0,0,0);
    float4 t1 = tail ? X[1*N4 + lane + 32] : make_float4(0,0,0,0);
    float4 t2 = tail ? X[2*N4 + lane + 32] : make_float4(0,0,0,0);
    float4 t3 = tail ? X[3*N4 + lane + 32] : make_float4(0,0,0,0);

    // ---- 1) tmp[b] = fixed-order sum of the 8 slice partials ----
    // 256 thr = 128 ch x 2 halves (4 partials each) -> shorter chain.
    {
        const int ch = t >> 1, half = t & 1;
        const int b  = bid >> 3;
        const float* p = g_tmp_part + (b * 8 + half * 4) * CH + ch;
        float a = __ldg(p) + __ldg(p + CH) + __ldg(p + 2*CH) + __ldg(p + 3*CH);
        a += __shfl_xor_sync(0xFFFFFFFFu, a, 1);        // combine halves
        if (half == 0) tmp_s[ch] = a;
    }
    __syncthreads();

    // ---- 2) zbn for this block's 32 channels (32 ch x 8 parts) ----
    {
        const int och = t >> 3, part = t & 7;
        const int o   = (bid & 7) * 32 + och;
        const float4* wz4 = reinterpret_cast<const float4*>(Wz)
                          + o * (CH / 4) + part * 4;
        const float4* tp4 = reinterpret_cast<const float4*>(tmp_s) + part * 4;
        float acc = 0.0f;
        #pragma unroll
        for (int i = 0; i < 4; i++) {
            const float4 w = wz4[i];
            const float4 v = tp4[i];
            acc += w.x * v.x + w.y * v.y + w.z * v.z + w.w * v.w;
        }
        acc += __shfl_xor_sync(0xFFFFFFFFu, acc, 1);
        acc += __shfl_xor_sync(0xFFFFFFFFu, acc, 2);
        acc += __shfl_xor_sync(0xFFFFFFFFu, acc, 4);
        if (part == 0) {
            const float s = rsqrtf(bn_v[o] + EPS) * bn_w[o];
            zloc[och] = acc * s + bn_b[o] - bn_m[o] * s;
        }
    }
    __syncthreads();

    // ---- 3) add + store (x values arrived during the preamble) ----
    const float z0 = zloc[lr + 0];
    const float z1 = zloc[lr + 1];
    const float z2 = zloc[lr + 2];
    const float z3 = zloc[lr + 3];

    a0.x += z0; a0.y += z0; a0.z += z0; a0.w += z0;
    a1.x += z1; a1.y += z1; a1.z += z1; a1.w += z1;
    a2.x += z2; a2.y += z2; a2.z += z2; a2.w += z2;
    a3.x += z3; a3.y += z3; a3.z += z3; a3.w += z3;
    O[0*N4 + lane] = a0;
    O[1*N4 + lane] = a1;
    O[2*N4 + lane] = a2;
    O[3*N4 + lane] = a3;

    if (tail) {
        t0.x += z0; t0.y += z0; t0.z += z0; t0.w += z0;
        t1.x += z1; t1.y += z1; t1.z += z1; t1.w += z1;
        t2.x += z2; t2.y += z2; t2.z += z2; t2.w += z2;
        t3.x += z3; t3.y += z3; t3.z += z3; t3.w += z3;
        O[0*N4 + lane + 32] = t0;
        O[1*N4 + lane + 32] = t1;
        O[2*N4 + lane + 32] = t2;
        O[3*N4 + lane + 32] = t3;
    }
}

// ---------------------------------------------------------------------------
// Inputs (metadata order):
//  0:x 1:y 2:Wq 3:Wk 4:Wv 5:Wz 6:bn_weight 7:bn_bias 8:bn_mean 9:bn_var
// ---------------------------------------------------------------------------
extern "C" void kernel_launch(void* const* d_in, const int* in_sizes, int n_in,
                              void* d_out, int out_size) {
    const float* x    = (const float*)d_in[0];
    const float* y    = (const float*)d_in[1];
    const float* Wv   = (const float*)d_in[4];
    const float* Wz   = (const float*)d_in[5];
    const float* bn_w = (const float*)d_in[6];
    const float* bn_b = (const float*)d_in[7];
    const float* bn_m = (const float*)d_in[8];
    const float* bn_v = (const float*)d_in[9];
    float* out = (float*)d_out;

    k1<<<K1_GRID, 512>>>(y, Wv);
    k2<<<K2_GRID, 256>>>(x, Wz, bn_w, bn_b, bn_m, bn_v, out);
}